// round 5
// baseline (speedup 1.0000x reference)
#include <cuda_runtime.h>

#define NN 4096
#define NV (NN/4)
#define RPB 8

// ping-pong iteration vectors + packed coefficient arrays
__device__ float  g_x[2][NN];
__device__ float4 g_coef[NN];   // per-column j: (d, p, q, -) for J update
__device__ float4 g_rowc[NN];   // per-row i:    (actX, Bn, pb, -)

// First matvec: x1 = b + 0.5*J*b  (x0 = b read directly; fills L2 with J)
__global__ void __launch_bounds__(128, 8) k_matvec1(const float* __restrict__ J,
                                                    const float* __restrict__ b) {
    int row = blockIdx.x;
    const float4* Jr = reinterpret_cast<const float4*>(J) + (size_t)row * NV;
    const float4* xv = reinterpret_cast<const float4*>(b);
    float s0 = 0.f, s1 = 0.f;
    int c = threadIdx.x;
    #pragma unroll 4
    for (int u = 0; u < 4; u++) {
        float4 a0 = Jr[c], v0 = xv[c];
        float4 a1 = Jr[c + 128], v1 = xv[c + 128];
        s0 = fmaf(a0.x, v0.x, s0); s0 = fmaf(a0.y, v0.y, s0);
        s0 = fmaf(a0.z, v0.z, s0); s0 = fmaf(a0.w, v0.w, s0);
        s1 = fmaf(a1.x, v1.x, s1); s1 = fmaf(a1.y, v1.y, s1);
        s1 = fmaf(a1.z, v1.z, s1); s1 = fmaf(a1.w, v1.w, s1);
        c += 256;
    }
    float sum = s0 + s1;
    #pragma unroll
    for (int o = 16; o; o >>= 1) sum += __shfl_down_sync(0xffffffffu, sum, o);
    __shared__ float s[4];
    if ((threadIdx.x & 31) == 0) s[threadIdx.x >> 5] = sum;
    __syncthreads();
    if (threadIdx.x == 0)
        g_x[1][row] = b[row] + 0.5f * (s[0] + s[1] + s[2] + s[3]);
}

// Warm matvec (J from L2) fused with streaming half the real_T_tilde update
// (DRAM work hides under the L2-bound matvec). Blocks [0,NN): matvec rows.
// Blocks [NN, NN+2048): rtt rows [rttBase, rttBase+2048).
__global__ void __launch_bounds__(128, 8) k_matvec_rtt(
        const float* __restrict__ J, const float* __restrict__ b,
        const float* __restrict__ rtt, const int* __restrict__ prev,
        const int* __restrict__ curr, float* __restrict__ outR,
        int src, int rttBase) {
    int bid = blockIdx.x;
    if (bid < NN) {
        int row = bid;
        const float4* Jr = reinterpret_cast<const float4*>(J) + (size_t)row * NV;
        const float4* xv = reinterpret_cast<const float4*>(g_x[src]);
        float s0 = 0.f, s1 = 0.f;
        int c = threadIdx.x;
        #pragma unroll 4
        for (int u = 0; u < 4; u++) {
            float4 a0 = Jr[c], v0 = xv[c];
            float4 a1 = Jr[c + 128], v1 = xv[c + 128];
            s0 = fmaf(a0.x, v0.x, s0); s0 = fmaf(a0.y, v0.y, s0);
            s0 = fmaf(a0.z, v0.z, s0); s0 = fmaf(a0.w, v0.w, s0);
            s1 = fmaf(a1.x, v1.x, s1); s1 = fmaf(a1.y, v1.y, s1);
            s1 = fmaf(a1.z, v1.z, s1); s1 = fmaf(a1.w, v1.w, s1);
            c += 256;
        }
        float sum = s0 + s1;
        #pragma unroll
        for (int o = 16; o; o >>= 1) sum += __shfl_down_sync(0xffffffffu, sum, o);
        __shared__ float s[4];
        if ((threadIdx.x & 31) == 0) s[threadIdx.x >> 5] = sum;
        __syncthreads();
        if (threadIdx.x == 0)
            g_x[src ^ 1][row] = b[row] + 0.5f * (s[0] + s[1] + s[2] + s[3]);
    } else {
        int row = rttBase + (bid - NN);
        float pb = (prev[row] > 0) ? 1.f : 0.f;
        const float4* Rr = reinterpret_cast<const float4*>(rtt) + (size_t)row * NV;
        const int4*   Cr = reinterpret_cast<const int4*>(curr);
        float4* Or = reinterpret_cast<float4*>(outR) + (size_t)row * NV;
        #pragma unroll 4
        for (int c = threadIdx.x; c < NV; c += 128) {
            float4 r = __ldcs(Rr + c);
            int4  cu = __ldg(Cr + c);
            float4 o;
            o.x = fmaf(pb, (cu.x > 0) ? 1.f : 0.f, 0.99f * r.x);
            o.y = fmaf(pb, (cu.y > 0) ? 1.f : 0.f, 0.99f * r.y);
            o.z = fmaf(pb, (cu.z > 0) ? 1.f : 0.f, 0.99f * r.z);
            o.w = fmaf(pb, (cu.w > 0) ? 1.f : 0.f, 0.99f * r.w);
            __stcs(Or + c, o);
        }
    }
}

// activity = 2*x_new - x_old (exact Perron cancellation), all O(N) outputs,
// plus packed per-row / per-column coefficient arrays for k_bigJ.
__global__ void k_small(const float* __restrict__ B_pos, const float* __restrict__ B_neg,
                        const float* __restrict__ eta_invs, const float* __restrict__ cnt,
                        const int* __restrict__ prev, const int* __restrict__ curr,
                        float* __restrict__ out) {
    int i = blockIdx.x * 256 + threadIdx.x;
    if (i >= NN) return;

    const size_t N  = NN;
    const size_t N2 = (size_t)NN * NN;
    const size_t oBp  = N + N2;
    const size_t oBn  = 2 * N + N2;
    const size_t oEta = 3 * N + N2;
    const size_t oCnt = 4 * N + 2 * N2;

    float a = 2.f * g_x[1][i] - g_x[0][i];   // x3 in g_x[1], x2 in g_x[0]
    out[i] = a;                              // activity

    float X = fminf(fmaxf(a, 0.f), 1.f);
    float act01 = (X >= 0.99f) ? 1.f : 0.f;

    const float lr_p = 0.1f / 0.12f;         // DT/TAU_POS
    float Bpn = fminf((1.f - lr_p) * B_pos[i] + lr_p * 7.0f * act01, 6.0f);
    const float lr_n = 0.1f / 1.0f;          // DT/TAU_NEG
    float Bnn = (1.f - lr_n) * B_neg[i];     // A_NEG = 0

    float pb = (prev[i] > 0) ? 1.f : 0.f;
    float ein = (float)prev[i] + 0.99f * eta_invs[i];
    float eta = 1.f / ein;

    out[oBp  + i] = Bpn;
    out[oBn  + i] = Bnn;
    out[oEta + i] = ein;
    out[oCnt + i] = 0.99f * cnt[i] + pb;

    float Bp   = (Bpn < 0.f) ? 0.f : Bpn;    // UPDATE_MIN = 0
    float Bn   = (Bnn < 0.f) ? 0.f : Bnn;
    float actX = (X < 0.99f) ? 0.f : X;
    int   upd  = (prev[i] == 1) ? 1 : 0;

    // off-diag: J' = clamp(d*J + actX[i]*p[j] + Bn[i]*q[j]); upd mask folded
    // branchlessly (d=1,p=q=0 leaves J unchanged; clamp is identity on [0,1]).
    g_coef[i] = upd ? make_float4(1.f - eta, eta * 1.008f * Bp, eta * 1.008f * actX, 0.f)
                    : make_float4(1.f, 0.f, 0.f, 0.f);
    g_rowc[i] = make_float4(actX, Bn, pb, 0.f);
}

// J plasticity update only (rtt handled in the warm matvecs). J reads hit L2;
// outJ streams to DRAM. Diagonal fixup folded in via the coefficient identity
// diag_term = actX[i] * p[i] * (0.165/1.008).
__global__ void __launch_bounds__(256) k_bigJ(const float* __restrict__ J,
                                              float* __restrict__ outJ) {
    int b = blockIdx.x;
    int jc = b & 3;
    int rowbase = (b >> 2) * RPB;
    int fj = jc * 256 + threadIdx.x;      // float4 index within row
    int j0 = fj << 2;

    const float4 c0 = g_coef[j0 + 0];
    const float4 c1 = g_coef[j0 + 1];
    const float4 c2 = g_coef[j0 + 2];
    const float4 c3 = g_coef[j0 + 3];

    #pragma unroll 4
    for (int r = 0; r < RPB; r++) {
        int i = rowbase + r;
        float4 rc = g_rowc[i];            // (actXi, Bni, pbi) — block-uniform
        size_t off = (size_t)i * NV + fj;
        float4 Jv = __ldg(reinterpret_cast<const float4*>(J) + off);

        float ja[4] = {Jv.x, Jv.y, Jv.z, Jv.w};
        float jo[4];
        jo[0] = fminf(fmaxf(fmaf(c0.x, ja[0], fmaf(rc.x, c0.y, rc.y * c0.z)), 0.f), 1.f);
        jo[1] = fminf(fmaxf(fmaf(c1.x, ja[1], fmaf(rc.x, c1.y, rc.y * c1.z)), 0.f), 1.f);
        jo[2] = fminf(fmaxf(fmaf(c2.x, ja[2], fmaf(rc.x, c2.y, rc.y * c2.z)), 0.f), 1.f);
        jo[3] = fminf(fmaxf(fmaf(c3.x, ja[3], fmaf(rc.x, c3.y, rc.y * c3.z)), 0.f), 1.f);

        if ((i >> 2) == fj) {             // this thread owns the diagonal element
            int jd = i & 3;
            float4 cd = (jd == 0) ? c0 : (jd == 1) ? c1 : (jd == 2) ? c2 : c3;
            jo[jd] = fminf(fmaxf(fmaf(cd.x, ja[jd],
                                      rc.x * cd.y * (0.165f / 1.008f)), 0.f), 1.f);
        }

        __stcs(reinterpret_cast<float4*>(outJ) + off,
               make_float4(jo[0], jo[1], jo[2], jo[3]));
    }
}

extern "C" void kernel_launch(void* const* d_in, const int* in_sizes, int n_in,
                              void* d_out, int out_size) {
    const float* inp      = (const float*)d_in[0];
    const float* J        = (const float*)d_in[1];
    const float* B_pos    = (const float*)d_in[2];
    const float* B_neg    = (const float*)d_in[3];
    const float* eta_invs = (const float*)d_in[4];
    const float* rtt      = (const float*)d_in[5];
    const float* cnt      = (const float*)d_in[6];
    const int*   prev     = (const int*)d_in[7];
    const int*   curr     = (const int*)d_in[8];
    float* out = (float*)d_out;

    const size_t N  = NN;
    const size_t N2 = (size_t)NN * NN;
    float* outJ = out + N;
    float* outR = out + 4 * N + N2;

    // 3 fixed-point iterations x <- b + 0.5*J*x with Richardson extrapolation
    // (exact Perron cancellation at lambda=0.5): truncation ~5e-8/element.
    k_matvec1<<<NN, 128>>>(J, inp);
    k_matvec_rtt<<<NN + 2048, 128>>>(J, inp, rtt, prev, curr, outR, 1, 0);
    k_matvec_rtt<<<NN + 2048, 128>>>(J, inp, rtt, prev, curr, outR, 0, 2048);

    k_small<<<NN / 256, 256>>>(B_pos, B_neg, eta_invs, cnt, prev, curr, out);

    k_bigJ<<<(NN / RPB) * 4, 256>>>(J, outJ);
}

// round 7
// speedup vs baseline: 1.0591x; 1.0591x over previous
#include <cuda_runtime.h>

#define NN 4096
#define NV (NN/4)
#define RPB 8

// ping-pong iteration vectors + packed coefficient arrays
__device__ float  g_x[2][NN];
__device__ float4 g_coef[NN];   // per-column j: (d, p, q, -) for J update
__device__ float4 g_rowc[NN];   // per-row i:    (actX, Bn, pb, -)

// First matvec: x1 = b + 0.5*J*b  (x0 = b read directly; fills L2 with J)
// 4 independent accumulator streams -> 16 LDG.128 in flight per thread.
__global__ void __launch_bounds__(128) k_matvec1(const float* __restrict__ J,
                                                 const float* __restrict__ b) {
    int row = blockIdx.x;
    const float4* Jr = reinterpret_cast<const float4*>(J) + (size_t)row * NV;
    const float4* xv = reinterpret_cast<const float4*>(b);
    float s0 = 0.f, s1 = 0.f, s2 = 0.f, s3 = 0.f;
    int c = threadIdx.x;
    #pragma unroll 2
    for (int u = 0; u < 2; u++) {
        float4 a0 = Jr[c],       v0 = xv[c];
        float4 a1 = Jr[c + 128], v1 = xv[c + 128];
        float4 a2 = Jr[c + 256], v2 = xv[c + 256];
        float4 a3 = Jr[c + 384], v3 = xv[c + 384];
        s0 = fmaf(a0.x, v0.x, s0); s0 = fmaf(a0.y, v0.y, s0);
        s0 = fmaf(a0.z, v0.z, s0); s0 = fmaf(a0.w, v0.w, s0);
        s1 = fmaf(a1.x, v1.x, s1); s1 = fmaf(a1.y, v1.y, s1);
        s1 = fmaf(a1.z, v1.z, s1); s1 = fmaf(a1.w, v1.w, s1);
        s2 = fmaf(a2.x, v2.x, s2); s2 = fmaf(a2.y, v2.y, s2);
        s2 = fmaf(a2.z, v2.z, s2); s2 = fmaf(a2.w, v2.w, s2);
        s3 = fmaf(a3.x, v3.x, s3); s3 = fmaf(a3.y, v3.y, s3);
        s3 = fmaf(a3.z, v3.z, s3); s3 = fmaf(a3.w, v3.w, s3);
        c += 512;
    }
    float sum = (s0 + s1) + (s2 + s3);
    #pragma unroll
    for (int o = 16; o; o >>= 1) sum += __shfl_down_sync(0xffffffffu, sum, o);
    __shared__ float s[4];
    if ((threadIdx.x & 31) == 0) s[threadIdx.x >> 5] = sum;
    __syncthreads();
    if (threadIdx.x == 0)
        g_x[1][row] = b[row] + 0.5f * (s[0] + s[1] + s[2] + s[3]);
}

// Warm matvec (J from L2) fused with streaming half of the real_T_tilde
// update. Block roles are INTERLEAVED (bid%3==2 -> rtt row) so the DRAM
// stream runs concurrently with the L2-bound matvec from the first wave to
// the last, instead of serializing as a tail phase.
__global__ void __launch_bounds__(128) k_matvec_rtt(
        const float* __restrict__ J, const float* __restrict__ b,
        const float* __restrict__ rtt, const int* __restrict__ prev,
        const int* __restrict__ curr, float* __restrict__ outR,
        int src, int rttBase) {
    int bid = blockIdx.x;
    int g = bid / 3;
    int r = bid - 3 * g;
    if (r < 2) {
        int row = 2 * g + r;
        const float4* Jr = reinterpret_cast<const float4*>(J) + (size_t)row * NV;
        const float4* xv = reinterpret_cast<const float4*>(g_x[src]);
        float s0 = 0.f, s1 = 0.f;
        int c = threadIdx.x;
        #pragma unroll 4
        for (int u = 0; u < 4; u++) {
            float4 a0 = Jr[c], v0 = xv[c];
            float4 a1 = Jr[c + 128], v1 = xv[c + 128];
            s0 = fmaf(a0.x, v0.x, s0); s0 = fmaf(a0.y, v0.y, s0);
            s0 = fmaf(a0.z, v0.z, s0); s0 = fmaf(a0.w, v0.w, s0);
            s1 = fmaf(a1.x, v1.x, s1); s1 = fmaf(a1.y, v1.y, s1);
            s1 = fmaf(a1.z, v1.z, s1); s1 = fmaf(a1.w, v1.w, s1);
            c += 256;
        }
        float sum = s0 + s1;
        #pragma unroll
        for (int o = 16; o; o >>= 1) sum += __shfl_down_sync(0xffffffffu, sum, o);
        __shared__ float s[4];
        if ((threadIdx.x & 31) == 0) s[threadIdx.x >> 5] = sum;
        __syncthreads();
        if (threadIdx.x == 0)
            g_x[src ^ 1][row] = b[row] + 0.5f * (s[0] + s[1] + s[2] + s[3]);
    } else {
        int row = rttBase + g;
        float pb = (prev[row] > 0) ? 1.f : 0.f;
        const float4* Rr = reinterpret_cast<const float4*>(rtt) + (size_t)row * NV;
        const int4*   Cr = reinterpret_cast<const int4*>(curr);
        float4* Or = reinterpret_cast<float4*>(outR) + (size_t)row * NV;
        #pragma unroll 4
        for (int c = threadIdx.x; c < NV; c += 128) {
            float4 rv = __ldcs(Rr + c);
            int4  cu = __ldg(Cr + c);
            float4 o;
            o.x = fmaf(pb, (cu.x > 0) ? 1.f : 0.f, 0.99f * rv.x);
            o.y = fmaf(pb, (cu.y > 0) ? 1.f : 0.f, 0.99f * rv.y);
            o.z = fmaf(pb, (cu.z > 0) ? 1.f : 0.f, 0.99f * rv.z);
            o.w = fmaf(pb, (cu.w > 0) ? 1.f : 0.f, 0.99f * rv.w);
            __stcs(Or + c, o);
        }
    }
}

// activity = 2*x_new - x_old (exact Perron cancellation), all O(N) outputs,
// plus packed per-row / per-column coefficient arrays for k_bigJ.
__global__ void k_small(const float* __restrict__ B_pos, const float* __restrict__ B_neg,
                        const float* __restrict__ eta_invs, const float* __restrict__ cnt,
                        const int* __restrict__ prev, const int* __restrict__ curr,
                        float* __restrict__ out) {
    int i = blockIdx.x * 128 + threadIdx.x;
    if (i >= NN) return;

    const size_t N  = NN;
    const size_t N2 = (size_t)NN * NN;
    const size_t oBp  = N + N2;
    const size_t oBn  = 2 * N + N2;
    const size_t oEta = 3 * N + N2;
    const size_t oCnt = 4 * N + 2 * N2;

    float a = 2.f * g_x[1][i] - g_x[0][i];   // x3 in g_x[1], x2 in g_x[0]
    out[i] = a;                              // activity

    float X = fminf(fmaxf(a, 0.f), 1.f);
    float act01 = (X >= 0.99f) ? 1.f : 0.f;

    const float lr_p = 0.1f / 0.12f;         // DT/TAU_POS
    float Bpn = fminf((1.f - lr_p) * B_pos[i] + lr_p * 7.0f * act01, 6.0f);
    const float lr_n = 0.1f / 1.0f;          // DT/TAU_NEG
    float Bnn = (1.f - lr_n) * B_neg[i];     // A_NEG = 0

    float pb = (prev[i] > 0) ? 1.f : 0.f;
    float ein = (float)prev[i] + 0.99f * eta_invs[i];
    float eta = 1.f / ein;

    out[oBp  + i] = Bpn;
    out[oBn  + i] = Bnn;
    out[oEta + i] = ein;
    out[oCnt + i] = 0.99f * cnt[i] + pb;

    float Bp   = (Bpn < 0.f) ? 0.f : Bpn;    // UPDATE_MIN = 0
    float Bn   = (Bnn < 0.f) ? 0.f : Bnn;
    float actX = (X < 0.99f) ? 0.f : X;
    int   upd  = (prev[i] == 1) ? 1 : 0;

    // off-diag: J' = clamp(d*J + actX[i]*p[j] + Bn[i]*q[j]); upd mask folded
    // branchlessly (d=1,p=q=0 leaves J unchanged; clamp is identity on [0,1]).
    g_coef[i] = upd ? make_float4(1.f - eta, eta * 1.008f * Bp, eta * 1.008f * actX, 0.f)
                    : make_float4(1.f, 0.f, 0.f, 0.f);
    g_rowc[i] = make_float4(actX, Bn, pb, 0.f);
}

// J plasticity update only (rtt handled in the warm matvecs). J reads hit L2;
// outJ streams to DRAM. Diagonal fixup folded in via the coefficient identity
// diag_term = actX[i] * p[i] * (0.165/1.008).
__global__ void __launch_bounds__(256) k_bigJ(const float* __restrict__ J,
                                              float* __restrict__ outJ) {
    int b = blockIdx.x;
    int jc = b & 3;
    int rowbase = (b >> 2) * RPB;
    int fj = jc * 256 + threadIdx.x;      // float4 index within row
    int j0 = fj << 2;

    const float4 c0 = g_coef[j0 + 0];
    const float4 c1 = g_coef[j0 + 1];
    const float4 c2 = g_coef[j0 + 2];
    const float4 c3 = g_coef[j0 + 3];

    #pragma unroll 4
    for (int r = 0; r < RPB; r++) {
        int i = rowbase + r;
        float4 rc = g_rowc[i];            // (actXi, Bni, pbi) — block-uniform
        size_t off = (size_t)i * NV + fj;
        float4 Jv = __ldg(reinterpret_cast<const float4*>(J) + off);

        float ja[4] = {Jv.x, Jv.y, Jv.z, Jv.w};
        float jo[4];
        jo[0] = fminf(fmaxf(fmaf(c0.x, ja[0], fmaf(rc.x, c0.y, rc.y * c0.z)), 0.f), 1.f);
        jo[1] = fminf(fmaxf(fmaf(c1.x, ja[1], fmaf(rc.x, c1.y, rc.y * c1.z)), 0.f), 1.f);
        jo[2] = fminf(fmaxf(fmaf(c2.x, ja[2], fmaf(rc.x, c2.y, rc.y * c2.z)), 0.f), 1.f);
        jo[3] = fminf(fmaxf(fmaf(c3.x, ja[3], fmaf(rc.x, c3.y, rc.y * c3.z)), 0.f), 1.f);

        if ((i >> 2) == fj) {             // this thread owns the diagonal element
            int jd = i & 3;
            float4 cd = (jd == 0) ? c0 : (jd == 1) ? c1 : (jd == 2) ? c2 : c3;
            jo[jd] = fminf(fmaxf(fmaf(cd.x, ja[jd],
                                      rc.x * cd.y * (0.165f / 1.008f)), 0.f), 1.f);
        }

        __stcs(reinterpret_cast<float4*>(outJ) + off,
               make_float4(jo[0], jo[1], jo[2], jo[3]));
    }
}

extern "C" void kernel_launch(void* const* d_in, const int* in_sizes, int n_in,
                              void* d_out, int out_size) {
    const float* inp      = (const float*)d_in[0];
    const float* J        = (const float*)d_in[1];
    const float* B_pos    = (const float*)d_in[2];
    const float* B_neg    = (const float*)d_in[3];
    const float* eta_invs = (const float*)d_in[4];
    const float* rtt      = (const float*)d_in[5];
    const float* cnt      = (const float*)d_in[6];
    const int*   prev     = (const int*)d_in[7];
    const int*   curr     = (const int*)d_in[8];
    float* out = (float*)d_out;

    const size_t N  = NN;
    const size_t N2 = (size_t)NN * NN;
    float* outJ = out + N;
    float* outR = out + 4 * N + N2;

    // 3 fixed-point iterations x <- b + 0.5*J*x with Richardson extrapolation
    // (exact Perron cancellation at lambda=0.5): truncation far below the
    // fp32 reference-noise floor.
    k_matvec1<<<NN, 128>>>(J, inp);
    k_matvec_rtt<<<6144, 128>>>(J, inp, rtt, prev, curr, outR, 1, 0);
    k_matvec_rtt<<<6144, 128>>>(J, inp, rtt, prev, curr, outR, 0, 2048);

    k_small<<<NN / 128, 128>>>(B_pos, B_neg, eta_invs, cnt, prev, curr, out);

    k_bigJ<<<(NN / RPB) * 4, 256>>>(J, outJ);
}

// round 8
// speedup vs baseline: 1.0777x; 1.0176x over previous
#include <cuda_runtime.h>

#define NN 4096
#define NV (NN/4)
#define RPB 8

// ping-pong iteration vectors + packed coefficient arrays
__device__ float  g_x[2][NN];
__device__ float4 g_coef[NN];   // per-column j: (d, p, q, -) for J update
__device__ float4 g_rowc[NN];   // per-row i:    (actX, Bn, pb, -)

// Independent real_T_tilde stream: out = 0.99*rtt + prev_b (x) curr_b.
// Launched FIRST with only 512 blocks (all immediately resident, ~20% of
// block slots) so the PDL-overlapped matvec chain can co-run on the same SMs.
__global__ void __launch_bounds__(256) k_rtt(const float* __restrict__ rtt,
                                             const int* __restrict__ prev,
                                             const int* __restrict__ curr,
                                             float* __restrict__ outR) {
    cudaTriggerProgrammaticLaunchCompletion();   // let mv1 launch immediately
    int rowbase = blockIdx.x * 8;
    const int4* Cr = reinterpret_cast<const int4*>(curr);
    #pragma unroll 2
    for (int r = 0; r < 8; r++) {
        int row = rowbase + r;
        float pb = (prev[row] > 0) ? 1.f : 0.f;
        const float4* Rr = reinterpret_cast<const float4*>(rtt) + (size_t)row * NV;
        float4* Or = reinterpret_cast<float4*>(outR) + (size_t)row * NV;
        #pragma unroll 4
        for (int c = threadIdx.x; c < NV; c += 256) {
            float4 rv = __ldcs(Rr + c);
            int4   cu = __ldg(Cr + c);
            float4 o;
            o.x = fmaf(pb, (cu.x > 0) ? 1.f : 0.f, 0.99f * rv.x);
            o.y = fmaf(pb, (cu.y > 0) ? 1.f : 0.f, 0.99f * rv.y);
            o.z = fmaf(pb, (cu.z > 0) ? 1.f : 0.f, 0.99f * rv.z);
            o.w = fmaf(pb, (cu.w > 0) ? 1.f : 0.f, 0.99f * rv.w);
            __stcs(Or + c, o);
        }
    }
}

// First matvec: x1 = b + 0.5*J*b. NO gridsync — independent of k_rtt, so it
// runs fully concurrent with the rtt stream.
__global__ void __launch_bounds__(128) k_matvec1(const float* __restrict__ J,
                                                 const float* __restrict__ b) {
    cudaTriggerProgrammaticLaunchCompletion();
    int row = blockIdx.x;
    const float4* Jr = reinterpret_cast<const float4*>(J) + (size_t)row * NV;
    const float4* xv = reinterpret_cast<const float4*>(b);
    float s0 = 0.f, s1 = 0.f, s2 = 0.f, s3 = 0.f;
    int c = threadIdx.x;
    #pragma unroll 2
    for (int u = 0; u < 2; u++) {
        float4 a0 = Jr[c],       v0 = xv[c];
        float4 a1 = Jr[c + 128], v1 = xv[c + 128];
        float4 a2 = Jr[c + 256], v2 = xv[c + 256];
        float4 a3 = Jr[c + 384], v3 = xv[c + 384];
        s0 = fmaf(a0.x, v0.x, s0); s0 = fmaf(a0.y, v0.y, s0);
        s0 = fmaf(a0.z, v0.z, s0); s0 = fmaf(a0.w, v0.w, s0);
        s1 = fmaf(a1.x, v1.x, s1); s1 = fmaf(a1.y, v1.y, s1);
        s1 = fmaf(a1.z, v1.z, s1); s1 = fmaf(a1.w, v1.w, s1);
        s2 = fmaf(a2.x, v2.x, s2); s2 = fmaf(a2.y, v2.y, s2);
        s2 = fmaf(a2.z, v2.z, s2); s2 = fmaf(a2.w, v2.w, s2);
        s3 = fmaf(a3.x, v3.x, s3); s3 = fmaf(a3.y, v3.y, s3);
        s3 = fmaf(a3.z, v3.z, s3); s3 = fmaf(a3.w, v3.w, s3);
        c += 512;
    }
    float sum = (s0 + s1) + (s2 + s3);
    #pragma unroll
    for (int o = 16; o; o >>= 1) sum += __shfl_down_sync(0xffffffffu, sum, o);
    __shared__ float s[4];
    if ((threadIdx.x & 31) == 0) s[threadIdx.x >> 5] = sum;
    __syncthreads();
    if (threadIdx.x == 0)
        g_x[1][row] = b[row] + 0.5f * (s[0] + s[1] + s[2] + s[3]);
}

// Warm matvec: y = b + 0.5*J*x, J from L2. Gridsyncs on predecessor (the
// previous matvec) before touching g_x.
__global__ void __launch_bounds__(128) k_matvec(const float* __restrict__ J,
                                                const float* __restrict__ b, int src) {
    cudaTriggerProgrammaticLaunchCompletion();
    cudaGridDependencySynchronize();
    int row = blockIdx.x;
    const float4* Jr = reinterpret_cast<const float4*>(J) + (size_t)row * NV;
    const float4* xv = reinterpret_cast<const float4*>(g_x[src]);
    float s0 = 0.f, s1 = 0.f;
    int c = threadIdx.x;
    #pragma unroll 4
    for (int u = 0; u < 4; u++) {
        float4 a0 = Jr[c], v0 = xv[c];
        float4 a1 = Jr[c + 128], v1 = xv[c + 128];
        s0 = fmaf(a0.x, v0.x, s0); s0 = fmaf(a0.y, v0.y, s0);
        s0 = fmaf(a0.z, v0.z, s0); s0 = fmaf(a0.w, v0.w, s0);
        s1 = fmaf(a1.x, v1.x, s1); s1 = fmaf(a1.y, v1.y, s1);
        s1 = fmaf(a1.z, v1.z, s1); s1 = fmaf(a1.w, v1.w, s1);
        c += 256;
    }
    float sum = s0 + s1;
    #pragma unroll
    for (int o = 16; o; o >>= 1) sum += __shfl_down_sync(0xffffffffu, sum, o);
    __shared__ float s[4];
    if ((threadIdx.x & 31) == 0) s[threadIdx.x >> 5] = sum;
    __syncthreads();
    if (threadIdx.x == 0)
        g_x[src ^ 1][row] = b[row] + 0.5f * (s[0] + s[1] + s[2] + s[3]);
}

// activity = 2*x_new - x_old (exact Perron cancellation), all O(N) outputs,
// plus packed per-row / per-column coefficient arrays for k_bigJ.
__global__ void k_small(const float* __restrict__ B_pos, const float* __restrict__ B_neg,
                        const float* __restrict__ eta_invs, const float* __restrict__ cnt,
                        const int* __restrict__ prev, const int* __restrict__ curr,
                        float* __restrict__ out) {
    cudaTriggerProgrammaticLaunchCompletion();
    cudaGridDependencySynchronize();
    int i = blockIdx.x * 128 + threadIdx.x;
    if (i >= NN) return;

    const size_t N  = NN;
    const size_t N2 = (size_t)NN * NN;
    const size_t oBp  = N + N2;
    const size_t oBn  = 2 * N + N2;
    const size_t oEta = 3 * N + N2;
    const size_t oCnt = 4 * N + 2 * N2;

    float a = 2.f * g_x[1][i] - g_x[0][i];   // x3 in g_x[1], x2 in g_x[0]
    out[i] = a;                              // activity

    float X = fminf(fmaxf(a, 0.f), 1.f);
    float act01 = (X >= 0.99f) ? 1.f : 0.f;

    const float lr_p = 0.1f / 0.12f;         // DT/TAU_POS
    float Bpn = fminf((1.f - lr_p) * B_pos[i] + lr_p * 7.0f * act01, 6.0f);
    const float lr_n = 0.1f / 1.0f;          // DT/TAU_NEG
    float Bnn = (1.f - lr_n) * B_neg[i];     // A_NEG = 0

    float pb = (prev[i] > 0) ? 1.f : 0.f;
    float ein = (float)prev[i] + 0.99f * eta_invs[i];
    float eta = 1.f / ein;

    out[oBp  + i] = Bpn;
    out[oBn  + i] = Bnn;
    out[oEta + i] = ein;
    out[oCnt + i] = 0.99f * cnt[i] + pb;

    float Bp   = (Bpn < 0.f) ? 0.f : Bpn;    // UPDATE_MIN = 0
    float Bn   = (Bnn < 0.f) ? 0.f : Bnn;
    float actX = (X < 0.99f) ? 0.f : X;
    int   upd  = (prev[i] == 1) ? 1 : 0;

    // off-diag: J' = clamp(d*J + actX[i]*p[j] + Bn[i]*q[j]); upd mask folded
    // branchlessly (d=1,p=q=0 leaves J unchanged; clamp is identity on [0,1]).
    g_coef[i] = upd ? make_float4(1.f - eta, eta * 1.008f * Bp, eta * 1.008f * actX, 0.f)
                    : make_float4(1.f, 0.f, 0.f, 0.f);
    g_rowc[i] = make_float4(actX, Bn, pb, 0.f);
}

// J plasticity update. J reads hit L2; outJ streams to DRAM. Diagonal fixup
// folded in via the identity diag_term = actX[i] * p[i] * (0.165/1.008).
__global__ void __launch_bounds__(256) k_bigJ(const float* __restrict__ J,
                                              float* __restrict__ outJ) {
    cudaGridDependencySynchronize();
    int b = blockIdx.x;
    int jc = b & 3;
    int rowbase = (b >> 2) * RPB;
    int fj = jc * 256 + threadIdx.x;      // float4 index within row
    int j0 = fj << 2;

    const float4 c0 = g_coef[j0 + 0];
    const float4 c1 = g_coef[j0 + 1];
    const float4 c2 = g_coef[j0 + 2];
    const float4 c3 = g_coef[j0 + 3];

    #pragma unroll 4
    for (int r = 0; r < RPB; r++) {
        int i = rowbase + r;
        float4 rc = g_rowc[i];            // (actXi, Bni, pbi) — block-uniform
        size_t off = (size_t)i * NV + fj;
        float4 Jv = __ldg(reinterpret_cast<const float4*>(J) + off);

        float ja[4] = {Jv.x, Jv.y, Jv.z, Jv.w};
        float jo[4];
        jo[0] = fminf(fmaxf(fmaf(c0.x, ja[0], fmaf(rc.x, c0.y, rc.y * c0.z)), 0.f), 1.f);
        jo[1] = fminf(fmaxf(fmaf(c1.x, ja[1], fmaf(rc.x, c1.y, rc.y * c1.z)), 0.f), 1.f);
        jo[2] = fminf(fmaxf(fmaf(c2.x, ja[2], fmaf(rc.x, c2.y, rc.y * c2.z)), 0.f), 1.f);
        jo[3] = fminf(fmaxf(fmaf(c3.x, ja[3], fmaf(rc.x, c3.y, rc.y * c3.z)), 0.f), 1.f);

        if ((i >> 2) == fj) {             // this thread owns the diagonal element
            int jd = i & 3;
            float4 cd = (jd == 0) ? c0 : (jd == 1) ? c1 : (jd == 2) ? c2 : c3;
            jo[jd] = fminf(fmaxf(fmaf(cd.x, ja[jd],
                                      rc.x * cd.y * (0.165f / 1.008f)), 0.f), 1.f);
        }

        __stcs(reinterpret_cast<float4*>(outJ) + off,
               make_float4(jo[0], jo[1], jo[2], jo[3]));
    }
}

// Launch with ProgrammaticStreamSerialization so blocks can prelaunch while
// the stream predecessor is still running; data deps enforced in-kernel via
// cudaGridDependencySynchronize().
template <typename... Args>
static void launch_pss(void (*kern)(Args...), dim3 grid, dim3 block, Args... args) {
    cudaLaunchConfig_t cfg = {};
    cfg.gridDim = grid;
    cfg.blockDim = block;
    cfg.dynamicSmemBytes = 0;
    cfg.stream = 0;
    cudaLaunchAttribute at[1];
    at[0].id = cudaLaunchAttributeProgrammaticStreamSerialization;
    at[0].val.programmaticStreamSerializationAllowed = 1;
    cfg.attrs = at;
    cfg.numAttrs = 1;
    cudaLaunchKernelEx(&cfg, kern, args...);
}

extern "C" void kernel_launch(void* const* d_in, const int* in_sizes, int n_in,
                              void* d_out, int out_size) {
    const float* inp      = (const float*)d_in[0];
    const float* J        = (const float*)d_in[1];
    const float* B_pos    = (const float*)d_in[2];
    const float* B_neg    = (const float*)d_in[3];
    const float* eta_invs = (const float*)d_in[4];
    const float* rtt      = (const float*)d_in[5];
    const float* cnt      = (const float*)d_in[6];
    const int*   prev     = (const int*)d_in[7];
    const int*   curr     = (const int*)d_in[8];
    float* out = (float*)d_out;

    const size_t N  = NN;
    const size_t N2 = (size_t)NN * NN;
    float* outJ = out + N;
    float* outR = out + 4 * N + N2;

    // Independent 128MB rtt stream launches first (512 resident blocks),
    // then the matvec chain co-runs with it via PDL. mv1 has no gridsync
    // (no dependency on k_rtt); mv2..k_bigJ gridsync on their true deps.
    k_rtt<<<512, 256>>>(rtt, prev, curr, outR);

    launch_pss(k_matvec1, dim3(NN), dim3(128), J, inp);
    launch_pss(k_matvec,  dim3(NN), dim3(128), J, inp, 1);
    launch_pss(k_matvec,  dim3(NN), dim3(128), J, inp, 0);
    launch_pss(k_small,   dim3(NN / 128), dim3(128),
               B_pos, B_neg, eta_invs, cnt, prev, curr, out);
    launch_pss(k_bigJ,    dim3((NN / RPB) * 4), dim3(256), J, outJ);
}